// round 14
// baseline (speedup 1.0000x reference)
#include <cuda_runtime.h>
#include <cuda_fp16.h>
#include <math.h>
#include <stdint.h>

#define BATCH 64
#define SENC  64
#define TDEC  31          // decoder steps = T-1
#define EMB   256
#define HID   512
#define G4    2048        // 4*H
#define VOC   32000
#define SNBLK 64          // persistent scan blocks (all resident)
#define NSTEP (SENC + TDEC)
#define MROWS (BATCH * TDEC)   // 1984 rows into FC
#define MPAD  2048             // padded FC rows (16 x 128)
#define KS16  (HID / 16)       // 32 k16-steps (FC / scan K)
#define EKS16 (EMB / 16)       // 16 k16-steps (xp K)
#define NT8   (VOC / 8)        // 4000 n8 tiles

// ---------------- scratch (device globals; no allocation) ----------------
__device__ float  d_xp_enc[SENC * BATCH * G4];   // [t][b][g] fp32
__device__ float  d_xp_dec[TDEC * BATCH * G4];
__device__ __half d_hbuf[2][BATCH * HID];        // ping-pong h (fp16)
__device__ __half d_hseq[MROWS * HID];           // decoder outputs (fp16)
__device__ unsigned d_flags[SNBLK];              // per-block generation flags

// fp16 fragment-major operands (packed half2 in uint32)
__device__ uint32_t d_Af[(MPAD / 16) * KS16 * 32 * 4];   // A: [mt][ks][lane][4]
__device__ uint32_t d_Bf[NT8 * KS16 * 32 * 2];           // B: [nt8][ks][lane][2]
__device__ uint32_t d_WihF[2 * 256 * EKS16 * 32 * 2];    // [layer][n8][ks][lane][2]
__device__ uint32_t d_WhhF[2 * SNBLK * 4 * KS16 * 32 * 2]; // [layer][bid][nt][ks][lane][2]

// ---------------- helpers ----------------
__device__ __forceinline__ uint32_t smem_u32(const void* p) {
    uint32_t a;
    asm("{ .reg .u64 t; cvta.to.shared.u64 t, %1; cvt.u32.u64 %0, t; }"
        : "=r"(a) : "l"(p));
    return a;
}
#define CP_ASYNC16(dst, src) \
    asm volatile("cp.async.cg.shared.global [%0], [%1], 16;" \
                 :: "r"(dst), "l"(src) : "memory")
#define CP_COMMIT() asm volatile("cp.async.commit_group;" ::: "memory")
#define CP_WAIT1()  asm volatile("cp.async.wait_group 1;" ::: "memory")
#define CP_WAITN(n) asm volatile("cp.async.wait_group %0;" :: "n"(n) : "memory")

__device__ __forceinline__ uint32_t packh2(float x, float y) {
    __half2 h = __floats2half2_rn(x, y);
    return *(uint32_t*)&h;
}
__device__ __forceinline__ void mma_f16(float* c, const uint32_t* a,
                                        uint32_t b0, uint32_t b1)
{
    asm volatile("mma.sync.aligned.m16n8k16.row.col.f32.f16.f16.f32 "
                 "{%0,%1,%2,%3}, {%4,%5,%6,%7}, {%8,%9}, {%0,%1,%2,%3};"
                 : "+f"(c[0]), "+f"(c[1]), "+f"(c[2]), "+f"(c[3])
                 : "r"(a[0]), "r"(a[1]), "r"(a[2]), "r"(a[3]), "r"(b0), "r"(b1));
}
__device__ __forceinline__ void ldmatrix_x4(uint32_t& r0, uint32_t& r1,
                                            uint32_t& r2, uint32_t& r3, uint32_t addr)
{
    asm volatile("ldmatrix.sync.aligned.m8n8.x4.shared.b16 {%0,%1,%2,%3}, [%4];"
                 : "=r"(r0), "=r"(r1), "=r"(r2), "=r"(r3) : "r"(addr));
}

// flag barrier: block bid arrives by storing gen to its own slot (no atomic
// contention); each warp polls all 64 slots (2 per lane) until all >= gen.
__device__ __forceinline__ void flag_arrive(int bid, unsigned gen) {
    asm volatile("st.release.gpu.global.u32 [%0], %1;"
                 :: "l"(&d_flags[bid]), "r"(gen) : "memory");
}
__device__ __forceinline__ void flag_poll(unsigned gen, int lane) {
    const unsigned* f = d_flags + lane * 2;
    unsigned v0, v1;
    do {
        asm volatile("ld.acquire.gpu.global.v2.u32 {%0,%1}, [%2];"
                     : "=r"(v0), "=r"(v1) : "l"(f) : "memory");
    } while (__any_sync(0xFFFFFFFFu, (v0 < gen) || (v1 < gen)));
}

// fast pointwise (MUFU-based; ~2^-21 rel err)
__device__ __forceinline__ float sigm(float x) {
    return __fdividef(1.0f, 1.0f + __expf(-x));
}
__device__ __forceinline__ float tanh_fast(float x) {
    return 1.0f - __fdividef(2.0f, __expf(2.0f * x) + 1.0f);
}

// ---------------- Wih -> fp16 fragments ----------------
__global__ __launch_bounds__(256) void convWih_frag_kernel(
    const float* __restrict__ encWih, const float* __restrict__ decWih)
{
    int idx = blockIdx.x * 256 + threadIdx.x;     // one uint2
    if (idx >= 2 * 256 * EKS16 * 32) return;
    int lane  = idx & 31;
    int ks    = (idx >> 5) & (EKS16 - 1);
    int nt    = (idx >> 9) & 255;
    int layer = idx >> 17;
    int g = lane >> 2, tig = lane & 3;
    const float* W = layer ? decWih : encWih;
    const float* row = W + (size_t)(nt * 8 + g) * EMB + ks * 16 + tig * 2;
    ((uint2*)d_WihF)[idx] = make_uint2(packh2(row[0], row[1]),
                                      packh2(row[8], row[9]));
}

// ---------------- xp via fp16 mma ----------------
#define XPP 264                     // smem pitch in halves
#define XP_SMEM (64 * XPP * 2)      // 33792 B

__global__ __launch_bounds__(256, 2) void xp_mma_kernel(
    const int*   __restrict__ src,  const int* __restrict__ tgt,
    const float* __restrict__ enc_emb, const float* __restrict__ dec_emb,
    const float* __restrict__ enc_bih, const float* __restrict__ enc_bhh,
    const float* __restrict__ dec_bih, const float* __restrict__ dec_bhh)
{
    extern __shared__ __half a_s[];

    const int tid  = threadIdx.x;
    const int wid  = tid >> 5;
    const int lane = tid & 31;
    const int n0   = blockIdx.x * 128;
    const int t    = blockIdx.y;

    const int*   toks; const float* emb; const float* bi; const float* bh;
    const uint32_t* WF; float* xp; int tloc, tstride;
    if (t < SENC) {
        toks = src; emb = enc_emb; bi = enc_bih; bh = enc_bhh;
        WF = d_WihF; xp = d_xp_enc + (size_t)t * BATCH * G4;
        tloc = t; tstride = SENC;
    } else {
        toks = tgt; emb = dec_emb; bi = dec_bih; bh = dec_bhh;
        WF = d_WihF + 256 * EKS16 * 32 * 2;
        xp = d_xp_dec + (size_t)(t - SENC) * BATCH * G4;
        tloc = t - SENC; tstride = 32;
    }

    // gather 64 emb rows -> fp16 smem (8192 half2)
#pragma unroll
    for (int i = 0; i < 32; i++) {
        int q  = tid + i * 256;
        int r  = q >> 7;
        int c2 = q & 127;
        int tok = __ldg(toks + r * tstride + tloc);
        float2 v = __ldg((const float2*)(emb + (size_t)tok * EMB + c2 * 2));
        *(uint32_t*)&a_s[r * XPP + c2 * 2] = packh2(v.x, v.y);
    }
    __syncthreads();

    const int mt = wid >> 1;
    const int nh = wid & 1;
    const int g  = lane >> 2, tig = lane & 3;

    float acc[8][4];
#pragma unroll
    for (int nt = 0; nt < 8; nt++)
#pragma unroll
        for (int r = 0; r < 4; r++) acc[nt][r] = 0.0f;

    const int n8base = n0 / 8 + nh * 8;
    const __half* ap = &a_s[(mt * 16 + g) * XPP + tig * 2];

    for (int ks = 0; ks < EKS16; ks++) {
        uint32_t a[4];
        a[0] = *(const uint32_t*)(ap + ks * 16);
        a[2] = *(const uint32_t*)(ap + ks * 16 + 8);
        a[1] = *(const uint32_t*)(ap + ks * 16 + 8 * XPP);
        a[3] = *(const uint32_t*)(ap + ks * 16 + 8 * XPP + 8);
#pragma unroll
        for (int nt = 0; nt < 8; nt++) {
            uint2 b = __ldg((const uint2*)(WF +
                      (((size_t)(n8base + nt) * EKS16 + ks) * 32 + lane) * 2));
            mma_f16(acc[nt], a, b.x, b.y);
        }
    }

#pragma unroll
    for (int nt = 0; nt < 8; nt++) {
        int n = (n8base + nt) * 8 + tig * 2;
        float b0 = __ldg(bi + n) + __ldg(bh + n);
        float b1 = __ldg(bi + n + 1) + __ldg(bh + n + 1);
        int r0 = mt * 16 + g;
        *(float2*)(xp + (size_t)r0 * G4 + n) =
            make_float2(acc[nt][0] + b0, acc[nt][1] + b1);
        *(float2*)(xp + (size_t)(r0 + 8) * G4 + n) =
            make_float2(acc[nt][2] + b0, acc[nt][3] + b1);
    }
}

// ---------------- Whh -> gate-permuted fp16 fragments (also resets flags) ----------------
__global__ __launch_bounds__(256) void convWhh_frag_kernel(
    const float* __restrict__ encWhh, const float* __restrict__ decWhh)
{
    if (blockIdx.x == 0 && threadIdx.x < SNBLK) d_flags[threadIdx.x] = 0;

    int idx = blockIdx.x * 256 + threadIdx.x;     // one uint2
    if (idx >= 2 * SNBLK * 4 * KS16 * 32) return;
    int lane  = idx & 31;
    int ks    = (idx >> 5) & (KS16 - 1);
    int nt    = (idx >> 10) & 3;
    int bid   = (idx >> 12) & 63;
    int layer = idx >> 18;

    int g = lane >> 2, tig = lane & 3;
    int nn   = nt * 8 + g;
    int j    = bid * 8 + (nn >> 2);
    int gate = nn & 3;
    const float* W = layer ? decWhh : encWhh;
    const float* row = W + (size_t)(gate * HID + j) * HID + ks * 16 + tig * 2;
    ((uint2*)d_WhhF)[idx] = make_uint2(packh2(row[0], row[1]),
                                      packh2(row[8], row[9]));
}

// ---------------- persistent LSTM scan, fp16 tensor cores, 64 blocks ----------------
#define HPB   1040                                   // h row pitch bytes
#define WFU   (4 * KS16 * 32 * 2)                    // 8192 u32 = 32 KB per layer
#define SCAN_SMEM (2 * WFU * 4 + 64 * HPB)           // 132096 B (both layers resident)

__global__ __launch_bounds__(256, 1) void scan_tc_kernel()
{
    extern __shared__ char scm[];
    uint32_t* wf = (uint32_t*)scm;                   // [2 layers] Whh frags
    char*     hs = scm + 2 * WFU * 4;                // [64 rows][HPB]
    const uint32_t hBase = smem_u32(hs);

    const int tid  = threadIdx.x;
    const int bid  = blockIdx.x;
    const int wid  = tid >> 5;
    const int lane = tid & 31;
    const int mt   = wid & 3;
    const int ntp  = (wid >> 2) * 2;
    const int g    = lane >> 2;
    const int tig  = lane & 3;
    const int odd  = lane & 1;

    const int row0 = mt * 16 + g;
    const int myb  = mt * 16 + g + odd * 8;
    const int j0   = bid * 8 + ntp * 2 + (tig >> 1);
    const int j1   = j0 + 2;

    // ldmatrix address for this lane's A fragments (per-chunk base added later)
    const uint32_t ldmBase = hBase + (uint32_t)((mt * 16 + (lane & 15)) * HPB
                                                + (lane >> 4) * 16);

    // h0 = 0
#pragma unroll
    for (int i = 0; i < 2; i++) {
        int e = tid + i * 256;
        d_hbuf[0][(e >> 3) * HID + bid * 8 + (e & 7)] = __float2half(0.0f);
    }
    float c0 = 0.0f, c1 = 0.0f;

    {   // BOTH layers' Whh frags upfront: 16384 u32 = 4096 uint4
        const uint4* se = (const uint4*)(d_WhhF + (size_t)bid * WFU);
        const uint4* sd = (const uint4*)(d_WhhF + (size_t)(SNBLK + bid) * WFU);
#pragma unroll
        for (int i = 0; i < 8; i++) {
            ((uint4*)wf)[tid + i * 256]        = se[tid + i * 256];
            ((uint4*)wf)[2048 + tid + i * 256] = sd[tid + i * 256];
        }
    }
    __syncthreads();

    // initial barrier: h0 visible everywhere (gen 1)
    if (tid == 0) flag_arrive(bid, 1u);
    flag_poll(1u, lane);

    // prefetch xp for step 0
    float xi0, xf0, xg0, xo0, xi1, xf1, xg1, xo1;
    {
        const float* xb0 = d_xp_enc + (size_t)myb * G4 + j0;
        const float* xb1 = d_xp_enc + (size_t)myb * G4 + j1;
        xi0 = __ldcg(xb0);        xf0 = __ldcg(xb0 + 512);
        xg0 = __ldcg(xb0 + 1024); xo0 = __ldcg(xb0 + 1536);
        xi1 = __ldcg(xb1);        xf1 = __ldcg(xb1 + 512);
        xg1 = __ldcg(xb1 + 1024); xo1 = __ldcg(xb1 + 1536);
    }

    for (int step = 0; step < NSTEP; step++) {
        const __half* __restrict__ hprev = d_hbuf[step & 1];
        __half*       __restrict__ hnext = d_hbuf[(step & 1) ^ 1];
        const uint32_t* wfL = wf + ((step < SENC) ? 0 : WFU);

        // stage h (fp16) in 2 chunks of 256 cols (512 B/row) via cp.async
#pragma unroll
        for (int ch = 0; ch < 2; ch++) {
#pragma unroll
            for (int i = 0; i < 8; i++) {
                int q  = tid + i * 256;              // 2048 16B-chunks per col-chunk
                int r  = q >> 5;
                int cb = (q & 31) * 16;
                CP_ASYNC16(hBase + r * HPB + ch * 512 + cb,
                           (const char*)hprev + (size_t)r * 1024 + ch * 512 + cb);
            }
            CP_COMMIT();
        }

        float acc[2][4];
#pragma unroll
        for (int u = 0; u < 2; u++)
#pragma unroll
            for (int r = 0; r < 4; r++) acc[u][r] = 0.0f;

#pragma unroll
        for (int ch = 0; ch < 2; ch++) {
            if (ch == 0) CP_WAITN(1);
            else CP_WAITN(0);
            __syncthreads();

            const uint32_t aAddr = ldmBase + ch * 512;
            const uint32_t* bp0 = wfL + ((ntp * KS16 + ch * 16) * 32 + lane) * 2;
            const uint32_t* bp1 = wfL + (((ntp + 1) * KS16 + ch * 16) * 32 + lane) * 2;
#pragma unroll
            for (int k2 = 0; k2 < 16; k2++) {       // 16 k16-steps per chunk
                uint32_t a[4];
                ldmatrix_x4(a[0], a[1], a[2], a[3], aAddr + k2 * 32);
                uint2 b0 = *(const uint2*)(bp0 + k2 * 64);
                uint2 b1 = *(const uint2*)(bp1 + k2 * 64);
                mma_f16(acc[0], a, b0.x, b0.y);
                mma_f16(acc[1], a, b1.x, b1.y);
            }
        }

        // gate reassembly + pointwise
        __half hr0h, hr1h;
#pragma unroll
        for (int u = 0; u < 2; u++) {
            float* a = acc[u];
            float o0 = __shfl_xor_sync(0xFFFFFFFFu, a[0], 1);
            float o1 = __shfl_xor_sync(0xFFFFFFFFu, a[1], 1);
            float o2 = __shfl_xor_sync(0xFFFFFFFFu, a[2], 1);
            float o3 = __shfl_xor_sync(0xFFFFFFFFu, a[3], 1);
            float pi, pf, pg, po;
            if (!odd) { pi = a[0]; pf = a[1]; pg = o0;   po = o1;   }
            else      { pi = o2;   pf = o3;   pg = a[2]; po = a[3]; }

            if (u == 0) { pi += xi0; pf += xf0; pg += xg0; po += xo0; }
            else        { pi += xi1; pf += xf1; pg += xg1; po += xo1; }

            float& cc = (u == 0) ? c0 : c1;
            cc = sigm(pf) * cc + sigm(pi) * tanh_fast(pg);
            __half hr = __float2half_rn(sigm(po) * tanh_fast(cc));

            int j = (u == 0) ? j0 : j1;
            __stcg((short*)&hnext[(size_t)myb * HID + j], *(short*)&hr);
            if (u == 0) hr0h = hr; else hr1h = hr;
        }

        // ---- flag barrier with work hidden in the poll shadow ----
        __syncthreads();                          // all hnext stores issued; hs reads done
        if (tid == 0) flag_arrive(bid, (unsigned)(step + 2));

        // overlapped work: hseq store + next-step xp prefetch
        if (step >= SENC) {
            int t = step - SENC;
            d_hseq[((size_t)myb * TDEC + t) * HID + j0] = hr0h;
            d_hseq[((size_t)myb * TDEC + t) * HID + j1] = hr1h;
        }
        if (step + 1 < NSTEP) {
            const float* xp_n = (step + 1 < SENC)
                ? (d_xp_enc + (size_t)(step + 1) * BATCH * G4)
                : (d_xp_dec + (size_t)(step + 1 - SENC) * BATCH * G4);
            const float* xb0 = xp_n + (size_t)myb * G4 + j0;
            const float* xb1 = xp_n + (size_t)myb * G4 + j1;
            xi0 = __ldcg(xb0);        xf0 = __ldcg(xb0 + 512);
            xg0 = __ldcg(xb0 + 1024); xo0 = __ldcg(xb0 + 1536);
            xi1 = __ldcg(xb1);        xf1 = __ldcg(xb1 + 512);
            xg1 = __ldcg(xb1 + 1024); xo1 = __ldcg(xb1 + 1536);

            // every warp polls independently -> no trailing __syncthreads
            flag_poll((unsigned)(step + 2), lane);
        }
    }
}

// ---------------- fragment gathers for the FC ----------------
__global__ __launch_bounds__(256) void convA_frag_kernel()
{
    int idx = blockIdx.x * 256 + threadIdx.x;        // one uint4
    const int total = (MPAD / 16) * KS16 * 32;
    if (idx >= total) return;
    int lane = idx & 31;
    int ks   = (idx >> 5) & (KS16 - 1);
    int mt   = idx / (32 * KS16);
    int g    = lane >> 2, tig = lane & 3;
    int m0   = mt * 16 + g;
    int k0   = ks * 16 + tig * 2;

    uint32_t a0 = 0, a1 = 0, a2 = 0, a3 = 0;
    if (m0 < MROWS) {
        a0 = *(const uint32_t*)&d_hseq[(size_t)m0 * HID + k0];
        a2 = *(const uint32_t*)&d_hseq[(size_t)m0 * HID + k0 + 8];
    }
    if (m0 + 8 < MROWS) {
        a1 = *(const uint32_t*)&d_hseq[(size_t)(m0 + 8) * HID + k0];
        a3 = *(const uint32_t*)&d_hseq[(size_t)(m0 + 8) * HID + k0 + 8];
    }
    ((uint4*)d_Af)[idx] = make_uint4(a0, a1, a2, a3);
}

__global__ __launch_bounds__(256) void convB_frag_kernel(const float* __restrict__ W)
{
    int idx = blockIdx.x * 256 + threadIdx.x;        // one uint2
    const int total = NT8 * KS16 * 32;
    if (idx >= total) return;
    int lane = idx & 31;
    int ks   = (idx >> 5) & (KS16 - 1);
    int nt   = idx / (32 * KS16);
    int g    = lane >> 2, tig = lane & 3;
    const float* row = W + (size_t)(nt * 8 + g) * HID + ks * 16 + tig * 2;
    ((uint2*)d_Bf)[idx] = make_uint2(packh2(row[0], row[1]),
                                    packh2(row[8], row[9]));
}

// ---------------- FC via fp16 mma.sync ----------------
#define FC_ITERS 8
#define ABUF 16384
#define BBUF 16384
#define FC_SMEM (2 * (ABUF + BBUF))   // 64 KB

__global__ __launch_bounds__(256, 2) void fc_mma_kernel(
    const float* __restrict__ bias, float* __restrict__ out)
{
    extern __shared__ char smem[];
    const uint32_t aBase = smem_u32(smem);
    const uint32_t bBase = aBase + 2 * ABUF;

    const int tid  = threadIdx.x;
    const int wid  = tid >> 5;
    const int lane = tid & 31;
    const int m0   = blockIdx.x * 128;     // fast dim: m-tiles share B via L2
    const int n0   = blockIdx.y * 128;

    const int mtW  = (wid >> 2) * 4;
    const int ntW  = (wid & 3) * 4;

    float acc[4][4][4];
#pragma unroll
    for (int mt = 0; mt < 4; mt++)
#pragma unroll
        for (int nt = 0; nt < 4; nt++)
#pragma unroll
            for (int r = 0; r < 4; r++) acc[mt][nt][r] = 0.0f;

    const int a_mtL  = tid >> 5;
    const int a_lane = tid & 31;
    const int b_ntL  = tid >> 4;
    const int b_in   = tid & 15;

#define LOAD_TILE(it, buf) do {                                                  \
    int _ks0 = (it) * 4;                                                         \
    const uint32_t* _ga = d_Af + (((size_t)(m0 / 16 + a_mtL) * KS16 + _ks0) * 128); \
    uint32_t _sa = aBase + (buf) * ABUF + (a_mtL * 4) * 512 + a_lane * 16;       \
    _Pragma("unroll")                                                            \
    for (int _c = 0; _c < 4; _c++)                                               \
        CP_ASYNC16(_sa + _c * 512, (const char*)(_ga + _c * 128 + a_lane * 4));  \
    const uint32_t* _gb = d_Bf + (((size_t)(n0 / 8 + b_ntL) * KS16 + _ks0) * 64); \
    uint32_t _sb = bBase + (buf) * BBUF + (b_ntL * 4) * 256 + b_in * 16;         \
    _Pragma("unroll")                                                            \
    for (int _c = 0; _c < 4; _c++)                                               \
        CP_ASYNC16(_sb + _c * 256, (const char*)(_gb + _c * 64 + b_in * 4));     \
} while (0)

    LOAD_TILE(0, 0);
    CP_COMMIT();

    for (int it = 0; it < FC_ITERS; it++) {
        const int buf = it & 1;
        if (it + 1 < FC_ITERS) LOAD_TILE(it + 1, buf ^ 1);
        CP_COMMIT();
        CP_WAIT1();
        __syncthreads();

        const uint32_t aOff = aBase + buf * ABUF;
        const uint32_t bOff = bBase + buf * BBUF;
#pragma unroll
        for (int ks = 0; ks < 4; ks++) {
            uint32_t a[4][4];
#pragma unroll
            for (int mt = 0; mt < 4; mt++) {
                uint32_t addr = aOff + ((mtW + mt) * 4 + ks) * 512 + lane * 16;
                asm volatile("ld.shared.v4.b32 {%0,%1,%2,%3}, [%4];"
                             : "=r"(a[mt][0]), "=r"(a[mt][1]),
                               "=r"(a[mt][2]), "=r"(a[mt][3]) : "r"(addr));
            }
            uint32_t b[4][2];
#pragma unroll
            for (int nt = 0; nt < 4; nt++) {
                uint32_t addr = bOff + ((ntW + nt) * 4 + ks) * 256 + lane * 8;
                asm volatile("ld.shared.v2.b32 {%0,%1}, [%2];"
                             : "=r"(b[nt][0]), "=r"(b[nt][1]) : "r"(addr));
            }
#pragma unroll
            for (int mt = 0; mt < 4; mt++)
#pragma unroll
                for (int nt = 0; nt < 4; nt++)
                    mma_f16(acc[mt][nt], a[mt], b[nt][0], b[nt][1]);
        }
        __syncthreads();
    }

    const int g   = lane >> 2;
    const int tig = lane & 3;
#pragma unroll
    for (int mt = 0; mt < 4; mt++) {
#pragma unroll
        for (int half = 0; half < 2; half++) {
            int m = m0 + (mtW + mt) * 16 + g + half * 8;
            if (m >= MROWS) continue;
            int bidx = m / TDEC;
            int tt   = m - bidx * TDEC;
            float* orow = out + ((size_t)bidx * 32 + tt + 1) * VOC;
#pragma unroll
            for (int nt = 0; nt < 4; nt++) {
                int n = n0 + (ntW + nt) * 8 + tig * 2;
                float b0 = __ldg(bias + n);
                float b1 = __ldg(bias + n + 1);
                float2 v = make_float2(acc[mt][nt][half * 2 + 0] + b0,
                                       acc[mt][nt][half * 2 + 1] + b1);
                *(float2*)(orow + n) = v;
            }
        }
    }
}

// ---------------- zero out[:, 0, :] ----------------
__global__ void zero_t0_kernel(float* __restrict__ out)
{
    int idx = blockIdx.x * blockDim.x + threadIdx.x;
    const int n4 = BATCH * (VOC / 4);
    if (idx < n4) {
        int b  = idx / (VOC / 4);
        int v4 = idx - b * (VOC / 4);
        ((float4*)(out + (size_t)b * 32 * VOC))[v4] = make_float4(0.f, 0.f, 0.f, 0.f);
    }
}

// ---------------- launch ----------------
extern "C" void kernel_launch(void* const* d_in, const int* in_sizes, int n_in,
                              void* d_out, int out_size)
{
    const int*   src     = (const int*)  d_in[0];
    const int*   tgt     = (const int*)  d_in[1];
    const float* enc_emb = (const float*)d_in[2];
    const float* dec_emb = (const float*)d_in[3];
    const float* enc_Wih = (const float*)d_in[4];
    const float* enc_Whh = (const float*)d_in[5];
    const float* enc_bih = (const float*)d_in[6];
    const float* enc_bhh = (const float*)d_in[7];
    const float* dec_Wih = (const float*)d_in[8];
    const float* dec_Whh = (const float*)d_in[9];
    const float* dec_bih = (const float*)d_in[10];
    const float* dec_bhh = (const float*)d_in[11];
    const float* fc_W    = (const float*)d_in[12];
    const float* fc_b    = (const float*)d_in[13];
    float* out = (float*)d_out;

    static int attr_set = 0;
    if (!attr_set) {
        cudaFuncSetAttribute(fc_mma_kernel,
                             cudaFuncAttributeMaxDynamicSharedMemorySize, FC_SMEM);
        cudaFuncSetAttribute(scan_tc_kernel,
                             cudaFuncAttributeMaxDynamicSharedMemorySize, SCAN_SMEM);
        cudaFuncSetAttribute(xp_mma_kernel,
                             cudaFuncAttributeMaxDynamicSharedMemorySize, XP_SMEM);
        attr_set = 1;
    }

    convWih_frag_kernel<<<(2 * 256 * EKS16 * 32 + 255) / 256, 256>>>(enc_Wih, dec_Wih);   // 1
    xp_mma_kernel<<<dim3(16, SENC + TDEC), 256, XP_SMEM>>>(
        src, tgt, enc_emb, dec_emb, enc_bih, enc_bhh, dec_bih, dec_bhh);                  // 2
    convWhh_frag_kernel<<<(2 * SNBLK * 4 * KS16 * 32 + 255) / 256, 256>>>(enc_Whh, dec_Whh); // 3 (+ flag reset)
    scan_tc_kernel<<<SNBLK, 256, SCAN_SMEM>>>();                                          // 4 <- ncu window
    convB_frag_kernel<<<(NT8 * KS16 * 32 + 255) / 256, 256>>>(fc_W);                      // 5
    convA_frag_kernel<<<((MPAD / 16) * KS16 * 32 + 255) / 256, 256>>>();                  // 6
    zero_t0_kernel<<<(BATCH * (VOC / 4) + 255) / 256, 256>>>(out);                        // 7
    fc_mma_kernel<<<dim3(MPAD / 128, VOC / 128), 256, FC_SMEM>>>(fc_b, out);              // 8
}

// round 15
// speedup vs baseline: 1.9193x; 1.9193x over previous
#include <cuda_runtime.h>
#include <cuda_fp16.h>
#include <math.h>
#include <stdint.h>

#define BATCH 64
#define SENC  64
#define TDEC  31          // decoder steps = T-1
#define EMB   256
#define HID   512
#define G4    2048        // 4*H
#define VOC   32000
#define SNBLK 64          // persistent scan blocks (all resident)
#define NSTEP (SENC + TDEC)
#define MROWS (BATCH * TDEC)   // 1984 rows into FC
#define MPAD  2048             // padded FC rows (16 x 128)
#define KS16  (HID / 16)       // 32 k16-steps (FC / scan K)
#define EKS16 (EMB / 16)       // 16 k16-steps (xp K)
#define NT8   (VOC / 8)        // 4000 n8 tiles

// ---------------- scratch (device globals; no allocation) ----------------
__device__ float  d_xp_enc[SENC * BATCH * G4];   // [t][b][g] fp32
__device__ float  d_xp_dec[TDEC * BATCH * G4];
__device__ __half d_hbuf[2][BATCH * HID];        // ping-pong h (fp16)
__device__ __half d_hseq[MROWS * HID];           // decoder outputs (fp16)
__device__ unsigned d_bar_ctr = 0;               // monotonic arrival counter

// fp16 fragment-major operands (packed half2 in uint32)
__device__ uint32_t d_Af[(MPAD / 16) * KS16 * 32 * 4];   // A: [mt][ks][lane][4]
__device__ uint32_t d_Bf[NT8 * KS16 * 32 * 2];           // B: [nt8][ks][lane][2]
__device__ uint32_t d_WihF[2 * 256 * EKS16 * 32 * 2];    // [layer][n8][ks][lane][2]
__device__ uint32_t d_WhhF[2 * SNBLK * 4 * KS16 * 32 * 2]; // [layer][bid][nt][ks][lane][2]

// ---------------- helpers ----------------
__device__ __forceinline__ uint32_t smem_u32(const void* p) {
    uint32_t a;
    asm("{ .reg .u64 t; cvta.to.shared.u64 t, %1; cvt.u32.u64 %0, t; }"
        : "=r"(a) : "l"(p));
    return a;
}
#define CP_ASYNC16(dst, src) \
    asm volatile("cp.async.cg.shared.global [%0], [%1], 16;" \
                 :: "r"(dst), "l"(src) : "memory")
#define CP_COMMIT() asm volatile("cp.async.commit_group;" ::: "memory")
#define CP_WAIT1()  asm volatile("cp.async.wait_group 1;" ::: "memory")
#define CP_WAITN(n) asm volatile("cp.async.wait_group %0;" :: "n"(n) : "memory")

__device__ __forceinline__ uint32_t packh2(float x, float y) {
    __half2 h = __floats2half2_rn(x, y);
    return *(uint32_t*)&h;
}
__device__ __forceinline__ void mma_f16(float* c, const uint32_t* a,
                                        uint32_t b0, uint32_t b1)
{
    asm volatile("mma.sync.aligned.m16n8k16.row.col.f32.f16.f16.f32 "
                 "{%0,%1,%2,%3}, {%4,%5,%6,%7}, {%8,%9}, {%0,%1,%2,%3};"
                 : "+f"(c[0]), "+f"(c[1]), "+f"(c[2]), "+f"(c[3])
                 : "r"(a[0]), "r"(a[1]), "r"(a[2]), "r"(a[3]), "r"(b0), "r"(b1));
}
__device__ __forceinline__ void ldmatrix_x4(uint32_t& r0, uint32_t& r1,
                                            uint32_t& r2, uint32_t& r3, uint32_t addr)
{
    asm volatile("ldmatrix.sync.aligned.m8n8.x4.shared.b16 {%0,%1,%2,%3}, [%4];"
                 : "=r"(r0), "=r"(r1), "=r"(r2), "=r"(r3) : "r"(addr));
}

// proven R13 barrier: monotonic counter, red.release arrive (no return),
// ONE poller per block, trailing __syncthreads outside.
__device__ __forceinline__ void bar_red_release() {
    asm volatile("red.release.gpu.global.add.u32 [%0], 1;"
                 :: "l"(&d_bar_ctr) : "memory");
}
__device__ __forceinline__ void bar_poll(unsigned target) {
    unsigned v;
    do {
        asm volatile("ld.acquire.gpu.global.u32 %0, [%1];"
                     : "=r"(v) : "l"(&d_bar_ctr) : "memory");
    } while (v < target);
}

// fast pointwise (MUFU-based; ~2^-21 rel err)
__device__ __forceinline__ float sigm(float x) {
    return __fdividef(1.0f, 1.0f + __expf(-x));
}
__device__ __forceinline__ float tanh_fast(float x) {
    return 1.0f - __fdividef(2.0f, __expf(2.0f * x) + 1.0f);
}

// ---------------- Wih -> fp16 fragments ----------------
__global__ __launch_bounds__(256) void convWih_frag_kernel(
    const float* __restrict__ encWih, const float* __restrict__ decWih)
{
    int idx = blockIdx.x * 256 + threadIdx.x;     // one uint2
    if (idx >= 2 * 256 * EKS16 * 32) return;
    int lane  = idx & 31;
    int ks    = (idx >> 5) & (EKS16 - 1);
    int nt    = (idx >> 9) & 255;
    int layer = idx >> 17;
    int g = lane >> 2, tig = lane & 3;
    const float* W = layer ? decWih : encWih;
    const float* row = W + (size_t)(nt * 8 + g) * EMB + ks * 16 + tig * 2;
    ((uint2*)d_WihF)[idx] = make_uint2(packh2(row[0], row[1]),
                                      packh2(row[8], row[9]));
}

// ---------------- xp via fp16 mma ----------------
#define XPP 264                     // smem pitch in halves
#define XP_SMEM (64 * XPP * 2)      // 33792 B

__global__ __launch_bounds__(256, 2) void xp_mma_kernel(
    const int*   __restrict__ src,  const int* __restrict__ tgt,
    const float* __restrict__ enc_emb, const float* __restrict__ dec_emb,
    const float* __restrict__ enc_bih, const float* __restrict__ enc_bhh,
    const float* __restrict__ dec_bih, const float* __restrict__ dec_bhh)
{
    extern __shared__ __half a_s[];

    const int tid  = threadIdx.x;
    const int wid  = tid >> 5;
    const int lane = tid & 31;
    const int n0   = blockIdx.x * 128;
    const int t    = blockIdx.y;

    const int*   toks; const float* emb; const float* bi; const float* bh;
    const uint32_t* WF; float* xp; int tloc, tstride;
    if (t < SENC) {
        toks = src; emb = enc_emb; bi = enc_bih; bh = enc_bhh;
        WF = d_WihF; xp = d_xp_enc + (size_t)t * BATCH * G4;
        tloc = t; tstride = SENC;
    } else {
        toks = tgt; emb = dec_emb; bi = dec_bih; bh = dec_bhh;
        WF = d_WihF + 256 * EKS16 * 32 * 2;
        xp = d_xp_dec + (size_t)(t - SENC) * BATCH * G4;
        tloc = t - SENC; tstride = 32;
    }

    // gather 64 emb rows -> fp16 smem (8192 half2)
#pragma unroll
    for (int i = 0; i < 32; i++) {
        int q  = tid + i * 256;
        int r  = q >> 7;
        int c2 = q & 127;
        int tok = __ldg(toks + r * tstride + tloc);
        float2 v = __ldg((const float2*)(emb + (size_t)tok * EMB + c2 * 2));
        *(uint32_t*)&a_s[r * XPP + c2 * 2] = packh2(v.x, v.y);
    }
    __syncthreads();

    const int mt = wid >> 1;
    const int nh = wid & 1;
    const int g  = lane >> 2, tig = lane & 3;

    float acc[8][4];
#pragma unroll
    for (int nt = 0; nt < 8; nt++)
#pragma unroll
        for (int r = 0; r < 4; r++) acc[nt][r] = 0.0f;

    const int n8base = n0 / 8 + nh * 8;
    const __half* ap = &a_s[(mt * 16 + g) * XPP + tig * 2];

    for (int ks = 0; ks < EKS16; ks++) {
        uint32_t a[4];
        a[0] = *(const uint32_t*)(ap + ks * 16);
        a[2] = *(const uint32_t*)(ap + ks * 16 + 8);
        a[1] = *(const uint32_t*)(ap + ks * 16 + 8 * XPP);
        a[3] = *(const uint32_t*)(ap + ks * 16 + 8 * XPP + 8);
#pragma unroll
        for (int nt = 0; nt < 8; nt++) {
            uint2 b = __ldg((const uint2*)(WF +
                      (((size_t)(n8base + nt) * EKS16 + ks) * 32 + lane) * 2));
            mma_f16(acc[nt], a, b.x, b.y);
        }
    }

#pragma unroll
    for (int nt = 0; nt < 8; nt++) {
        int n = (n8base + nt) * 8 + tig * 2;
        float b0 = __ldg(bi + n) + __ldg(bh + n);
        float b1 = __ldg(bi + n + 1) + __ldg(bh + n + 1);
        int r0 = mt * 16 + g;
        *(float2*)(xp + (size_t)r0 * G4 + n) =
            make_float2(acc[nt][0] + b0, acc[nt][1] + b1);
        *(float2*)(xp + (size_t)(r0 + 8) * G4 + n) =
            make_float2(acc[nt][2] + b0, acc[nt][3] + b1);
    }
}

// ---------------- Whh -> gate-permuted fp16 fragments (also resets barrier ctr) ----------------
__global__ __launch_bounds__(256) void convWhh_frag_kernel(
    const float* __restrict__ encWhh, const float* __restrict__ decWhh)
{
    if (blockIdx.x == 0 && threadIdx.x == 0) d_bar_ctr = 0;   // per-launch reset

    int idx = blockIdx.x * 256 + threadIdx.x;     // one uint2
    if (idx >= 2 * SNBLK * 4 * KS16 * 32) return;
    int lane  = idx & 31;
    int ks    = (idx >> 5) & (KS16 - 1);
    int nt    = (idx >> 10) & 3;
    int bid   = (idx >> 12) & 63;
    int layer = idx >> 18;

    int g = lane >> 2, tig = lane & 3;
    int nn   = nt * 8 + g;
    int j    = bid * 8 + (nn >> 2);
    int gate = nn & 3;
    const float* W = layer ? decWhh : encWhh;
    const float* row = W + (size_t)(gate * HID + j) * HID + ks * 16 + tig * 2;
    ((uint2*)d_WhhF)[idx] = make_uint2(packh2(row[0], row[1]),
                                      packh2(row[8], row[9]));
}

// ---------------- persistent LSTM scan, fp16 tensor cores, 64 blocks ----------------
#define HPB   1040                                   // h row pitch bytes
#define WFU   (4 * KS16 * 32 * 2)                    // 8192 u32 = 32 KB per layer
#define SCAN_SMEM (2 * WFU * 4 + 64 * HPB)           // 132096 B (both layers resident)

__global__ __launch_bounds__(256, 1) void scan_tc_kernel()
{
    extern __shared__ char scm[];
    uint32_t* wf = (uint32_t*)scm;                   // [2 layers] Whh frags
    char*     hs = scm + 2 * WFU * 4;                // [64 rows][HPB]
    const uint32_t hBase = smem_u32(hs);

    const int tid  = threadIdx.x;
    const int bid  = blockIdx.x;
    const int wid  = tid >> 5;
    const int lane = tid & 31;
    const int mt   = wid & 3;
    const int ntp  = (wid >> 2) * 2;
    const int g    = lane >> 2;
    const int tig  = lane & 3;
    const int odd  = lane & 1;

    const int row0 = mt * 16 + g;
    const int myb  = mt * 16 + g + odd * 8;
    const int j0   = bid * 8 + ntp * 2 + (tig >> 1);
    const int j1   = j0 + 2;

    // ldmatrix address for this lane's A fragments (per-chunk base added later)
    const uint32_t ldmBase = hBase + (uint32_t)((mt * 16 + (lane & 15)) * HPB
                                                + (lane >> 4) * 16);

    // h0 = 0
#pragma unroll
    for (int i = 0; i < 2; i++) {
        int e = tid + i * 256;
        d_hbuf[0][(e >> 3) * HID + bid * 8 + (e & 7)] = __float2half(0.0f);
    }
    float c0 = 0.0f, c1 = 0.0f;

    {   // BOTH layers' Whh frags upfront: 16384 u32 = 4096 uint4
        const uint4* se = (const uint4*)(d_WhhF + (size_t)bid * WFU);
        const uint4* sd = (const uint4*)(d_WhhF + (size_t)(SNBLK + bid) * WFU);
#pragma unroll
        for (int i = 0; i < 8; i++) {
            ((uint4*)wf)[tid + i * 256]        = se[tid + i * 256];
            ((uint4*)wf)[2048 + tid + i * 256] = sd[tid + i * 256];
        }
    }
    __syncthreads();

    unsigned bar_target = SNBLK;
    // initial barrier: h0 visible everywhere
    if (tid == 0) { bar_red_release(); bar_poll(bar_target); }
    bar_target += SNBLK;
    __syncthreads();

    // prefetch xp for step 0
    float xi0, xf0, xg0, xo0, xi1, xf1, xg1, xo1;
    {
        const float* xb0 = d_xp_enc + (size_t)myb * G4 + j0;
        const float* xb1 = d_xp_enc + (size_t)myb * G4 + j1;
        xi0 = __ldcg(xb0);        xf0 = __ldcg(xb0 + 512);
        xg0 = __ldcg(xb0 + 1024); xo0 = __ldcg(xb0 + 1536);
        xi1 = __ldcg(xb1);        xf1 = __ldcg(xb1 + 512);
        xg1 = __ldcg(xb1 + 1024); xo1 = __ldcg(xb1 + 1536);
    }

    for (int step = 0; step < NSTEP; step++) {
        const __half* __restrict__ hprev = d_hbuf[step & 1];
        __half*       __restrict__ hnext = d_hbuf[(step & 1) ^ 1];
        const uint32_t* wfL = wf + ((step < SENC) ? 0 : WFU);

        // stage h (fp16) in 2 chunks of 256 cols (512 B/row) via cp.async
#pragma unroll
        for (int ch = 0; ch < 2; ch++) {
#pragma unroll
            for (int i = 0; i < 8; i++) {
                int q  = tid + i * 256;              // 2048 16B-chunks per col-chunk
                int r  = q >> 5;
                int cb = (q & 31) * 16;
                CP_ASYNC16(hBase + r * HPB + ch * 512 + cb,
                           (const char*)hprev + (size_t)r * 1024 + ch * 512 + cb);
            }
            CP_COMMIT();
        }

        float acc[2][4];
#pragma unroll
        for (int u = 0; u < 2; u++)
#pragma unroll
            for (int r = 0; r < 4; r++) acc[u][r] = 0.0f;

#pragma unroll
        for (int ch = 0; ch < 2; ch++) {
            if (ch == 0) CP_WAITN(1);
            else CP_WAITN(0);
            __syncthreads();

            const uint32_t aAddr = ldmBase + ch * 512;
            const uint32_t* bp0 = wfL + ((ntp * KS16 + ch * 16) * 32 + lane) * 2;
            const uint32_t* bp1 = wfL + (((ntp + 1) * KS16 + ch * 16) * 32 + lane) * 2;
#pragma unroll
            for (int k2 = 0; k2 < 16; k2++) {       // 16 k16-steps per chunk
                uint32_t a[4];
                ldmatrix_x4(a[0], a[1], a[2], a[3], aAddr + k2 * 32);
                uint2 b0 = *(const uint2*)(bp0 + k2 * 64);
                uint2 b1 = *(const uint2*)(bp1 + k2 * 64);
                mma_f16(acc[0], a, b0.x, b0.y);
                mma_f16(acc[1], a, b1.x, b1.y);
            }
        }

        // gate reassembly + pointwise
        __half hr0h, hr1h;
#pragma unroll
        for (int u = 0; u < 2; u++) {
            float* a = acc[u];
            float o0 = __shfl_xor_sync(0xFFFFFFFFu, a[0], 1);
            float o1 = __shfl_xor_sync(0xFFFFFFFFu, a[1], 1);
            float o2 = __shfl_xor_sync(0xFFFFFFFFu, a[2], 1);
            float o3 = __shfl_xor_sync(0xFFFFFFFFu, a[3], 1);
            float pi, pf, pg, po;
            if (!odd) { pi = a[0]; pf = a[1]; pg = o0;   po = o1;   }
            else      { pi = o2;   pf = o3;   pg = a[2]; po = a[3]; }

            if (u == 0) { pi += xi0; pf += xf0; pg += xg0; po += xo0; }
            else        { pi += xi1; pf += xf1; pg += xg1; po += xo1; }

            float& cc = (u == 0) ? c0 : c1;
            cc = sigm(pf) * cc + sigm(pi) * tanh_fast(pg);
            __half hr = __float2half_rn(sigm(po) * tanh_fast(cc));

            int j = (u == 0) ? j0 : j1;
            __stcg((short*)&hnext[(size_t)myb * HID + j], *(short*)&hr);
            if (u == 0) hr0h = hr; else hr1h = hr;
        }

        // ---- barrier with work hidden in the poll shadow (skip after last step) ----
        __syncthreads();                      // all hnext stores issued; hs reads done
        const bool last = (step + 1 == NSTEP);
        if (!last && tid == 0) bar_red_release();   // arrive

        // overlapped work: hseq store + next-step xp prefetch
        if (step >= SENC) {
            int t = step - SENC;
            d_hseq[((size_t)myb * TDEC + t) * HID + j0] = hr0h;
            d_hseq[((size_t)myb * TDEC + t) * HID + j1] = hr1h;
        }
        if (!last) {
            const float* xp_n = (step + 1 < SENC)
                ? (d_xp_enc + (size_t)(step + 1) * BATCH * G4)
                : (d_xp_dec + (size_t)(step + 1 - SENC) * BATCH * G4);
            const float* xb0 = xp_n + (size_t)myb * G4 + j0;
            const float* xb1 = xp_n + (size_t)myb * G4 + j1;
            xi0 = __ldcg(xb0);        xf0 = __ldcg(xb0 + 512);
            xg0 = __ldcg(xb0 + 1024); xo0 = __ldcg(xb0 + 1536);
            xi1 = __ldcg(xb1);        xf1 = __ldcg(xb1 + 512);
            xg1 = __ldcg(xb1 + 1024); xo1 = __ldcg(xb1 + 1536);

            if (tid == 0) bar_poll(bar_target);     // release detection (1 poller)
            bar_target += SNBLK;
            __syncthreads();
        }
    }
}

// ---------------- fragment gathers for the FC ----------------
__global__ __launch_bounds__(256) void convA_frag_kernel()
{
    int idx = blockIdx.x * 256 + threadIdx.x;        // one uint4
    const int total = (MPAD / 16) * KS16 * 32;
    if (idx >= total) return;
    int lane = idx & 31;
    int ks   = (idx >> 5) & (KS16 - 1);
    int mt   = idx / (32 * KS16);
    int g    = lane >> 2, tig = lane & 3;
    int m0   = mt * 16 + g;
    int k0   = ks * 16 + tig * 2;

    uint32_t a0 = 0, a1 = 0, a2 = 0, a3 = 0;
    if (m0 < MROWS) {
        a0 = *(const uint32_t*)&d_hseq[(size_t)m0 * HID + k0];
        a2 = *(const uint32_t*)&d_hseq[(size_t)m0 * HID + k0 + 8];
    }
    if (m0 + 8 < MROWS) {
        a1 = *(const uint32_t*)&d_hseq[(size_t)(m0 + 8) * HID + k0];
        a3 = *(const uint32_t*)&d_hseq[(size_t)(m0 + 8) * HID + k0 + 8];
    }
    ((uint4*)d_Af)[idx] = make_uint4(a0, a1, a2, a3);
}

__global__ __launch_bounds__(256) void convB_frag_kernel(const float* __restrict__ W)
{
    int idx = blockIdx.x * 256 + threadIdx.x;        // one uint2
    const int total = NT8 * KS16 * 32;
    if (idx >= total) return;
    int lane = idx & 31;
    int ks   = (idx >> 5) & (KS16 - 1);
    int nt   = idx / (32 * KS16);
    int g    = lane >> 2, tig = lane & 3;
    const float* row = W + (size_t)(nt * 8 + g) * HID + ks * 16 + tig * 2;
    ((uint2*)d_Bf)[idx] = make_uint2(packh2(row[0], row[1]),
                                    packh2(row[8], row[9]));
}

// ---------------- FC via fp16 mma.sync ----------------
#define FC_ITERS 8
#define ABUF 16384
#define BBUF 16384
#define FC_SMEM (2 * (ABUF + BBUF))   // 64 KB

__global__ __launch_bounds__(256, 2) void fc_mma_kernel(
    const float* __restrict__ bias, float* __restrict__ out)
{
    extern __shared__ char smem[];
    const uint32_t aBase = smem_u32(smem);
    const uint32_t bBase = aBase + 2 * ABUF;

    const int tid  = threadIdx.x;
    const int wid  = tid >> 5;
    const int lane = tid & 31;
    const int m0   = blockIdx.x * 128;     // fast dim: m-tiles share B via L2
    const int n0   = blockIdx.y * 128;

    const int mtW  = (wid >> 2) * 4;
    const int ntW  = (wid & 3) * 4;

    float acc[4][4][4];
#pragma unroll
    for (int mt = 0; mt < 4; mt++)
#pragma unroll
        for (int nt = 0; nt < 4; nt++)
#pragma unroll
            for (int r = 0; r < 4; r++) acc[mt][nt][r] = 0.0f;

    const int a_mtL  = tid >> 5;
    const int a_lane = tid & 31;
    const int b_ntL  = tid >> 4;
    const int b_in   = tid & 15;

#define LOAD_TILE(it, buf) do {                                                  \
    int _ks0 = (it) * 4;                                                         \
    const uint32_t* _ga = d_Af + (((size_t)(m0 / 16 + a_mtL) * KS16 + _ks0) * 128); \
    uint32_t _sa = aBase + (buf) * ABUF + (a_mtL * 4) * 512 + a_lane * 16;       \
    _Pragma("unroll")                                                            \
    for (int _c = 0; _c < 4; _c++)                                               \
        CP_ASYNC16(_sa + _c * 512, (const char*)(_ga + _c * 128 + a_lane * 4));  \
    const uint32_t* _gb = d_Bf + (((size_t)(n0 / 8 + b_ntL) * KS16 + _ks0) * 64); \
    uint32_t _sb = bBase + (buf) * BBUF + (b_ntL * 4) * 256 + b_in * 16;         \
    _Pragma("unroll")                                                            \
    for (int _c = 0; _c < 4; _c++)                                               \
        CP_ASYNC16(_sb + _c * 256, (const char*)(_gb + _c * 64 + b_in * 4));     \
} while (0)

    LOAD_TILE(0, 0);
    CP_COMMIT();

    for (int it = 0; it < FC_ITERS; it++) {
        const int buf = it & 1;
        if (it + 1 < FC_ITERS) LOAD_TILE(it + 1, buf ^ 1);
        CP_COMMIT();
        CP_WAIT1();
        __syncthreads();

        const uint32_t aOff = aBase + buf * ABUF;
        const uint32_t bOff = bBase + buf * BBUF;
#pragma unroll
        for (int ks = 0; ks < 4; ks++) {
            uint32_t a[4][4];
#pragma unroll
            for (int mt = 0; mt < 4; mt++) {
                uint32_t addr = aOff + ((mtW + mt) * 4 + ks) * 512 + lane * 16;
                asm volatile("ld.shared.v4.b32 {%0,%1,%2,%3}, [%4];"
                             : "=r"(a[mt][0]), "=r"(a[mt][1]),
                               "=r"(a[mt][2]), "=r"(a[mt][3]) : "r"(addr));
            }
            uint32_t b[4][2];
#pragma unroll
            for (int nt = 0; nt < 4; nt++) {
                uint32_t addr = bOff + ((ntW + nt) * 4 + ks) * 256 + lane * 8;
                asm volatile("ld.shared.v2.b32 {%0,%1}, [%2];"
                             : "=r"(b[nt][0]), "=r"(b[nt][1]) : "r"(addr));
            }
#pragma unroll
            for (int mt = 0; mt < 4; mt++)
#pragma unroll
                for (int nt = 0; nt < 4; nt++)
                    mma_f16(acc[mt][nt], a[mt], b[nt][0], b[nt][1]);
        }
        __syncthreads();
    }

    const int g   = lane >> 2;
    const int tig = lane & 3;
#pragma unroll
    for (int mt = 0; mt < 4; mt++) {
#pragma unroll
        for (int half = 0; half < 2; half++) {
            int m = m0 + (mtW + mt) * 16 + g + half * 8;
            if (m >= MROWS) continue;
            int bidx = m / TDEC;
            int tt   = m - bidx * TDEC;
            float* orow = out + ((size_t)bidx * 32 + tt + 1) * VOC;
#pragma unroll
            for (int nt = 0; nt < 4; nt++) {
                int n = n0 + (ntW + nt) * 8 + tig * 2;
                float b0 = __ldg(bias + n);
                float b1 = __ldg(bias + n + 1);
                float2 v = make_float2(acc[mt][nt][half * 2 + 0] + b0,
                                       acc[mt][nt][half * 2 + 1] + b1);
                *(float2*)(orow + n) = v;
            }
        }
    }
}

// ---------------- zero out[:, 0, :] ----------------
__global__ void zero_t0_kernel(float* __restrict__ out)
{
    int idx = blockIdx.x * blockDim.x + threadIdx.x;
    const int n4 = BATCH * (VOC / 4);
    if (idx < n4) {
        int b  = idx / (VOC / 4);
        int v4 = idx - b * (VOC / 4);
        ((float4*)(out + (size_t)b * 32 * VOC))[v4] = make_float4(0.f, 0.f, 0.f, 0.f);
    }
}

// ---------------- launch ----------------
extern "C" void kernel_launch(void* const* d_in, const int* in_sizes, int n_in,
                              void* d_out, int out_size)
{
    const int*   src     = (const int*)  d_in[0];
    const int*   tgt     = (const int*)  d_in[1];
    const float* enc_emb = (const float*)d_in[2];
    const float* dec_emb = (const float*)d_in[3];
    const float* enc_Wih = (const float*)d_in[4];
    const float* enc_Whh = (const float*)d_in[5];
    const float* enc_bih = (const float*)d_in[6];
    const float* enc_bhh = (const float*)d_in[7];
    const float* dec_Wih = (const float*)d_in[8];
    const float* dec_Whh = (const float*)d_in[9];
    const float* dec_bih = (const float*)d_in[10];
    const float* dec_bhh = (const float*)d_in[11];
    const float* fc_W    = (const float*)d_in[12];
    const float* fc_b    = (const float*)d_in[13];
    float* out = (float*)d_out;

    static int attr_set = 0;
    if (!attr_set) {
        cudaFuncSetAttribute(fc_mma_kernel,
                             cudaFuncAttributeMaxDynamicSharedMemorySize, FC_SMEM);
        cudaFuncSetAttribute(scan_tc_kernel,
                             cudaFuncAttributeMaxDynamicSharedMemorySize, SCAN_SMEM);
        cudaFuncSetAttribute(xp_mma_kernel,
                             cudaFuncAttributeMaxDynamicSharedMemorySize, XP_SMEM);
        attr_set = 1;
    }

    convWih_frag_kernel<<<(2 * 256 * EKS16 * 32 + 255) / 256, 256>>>(enc_Wih, dec_Wih);   // 1
    xp_mma_kernel<<<dim3(16, SENC + TDEC), 256, XP_SMEM>>>(
        src, tgt, enc_emb, dec_emb, enc_bih, enc_bhh, dec_bih, dec_bhh);                  // 2
    convWhh_frag_kernel<<<(2 * SNBLK * 4 * KS16 * 32 + 255) / 256, 256>>>(enc_Whh, dec_Whh); // 3 (+ ctr reset)
    scan_tc_kernel<<<SNBLK, 256, SCAN_SMEM>>>();                                          // 4 <- ncu window
    convB_frag_kernel<<<(NT8 * KS16 * 32 + 255) / 256, 256>>>(fc_W);                      // 5
    convA_frag_kernel<<<((MPAD / 16) * KS16 * 32 + 255) / 256, 256>>>();                  // 6
    zero_t0_kernel<<<(BATCH * (VOC / 4) + 255) / 256, 256>>>(out);                        // 7
    fc_mma_kernel<<<dim3(MPAD / 128, VOC / 128), 256, FC_SMEM>>>(fc_b, out);              // 8
}